// round 3
// baseline (speedup 1.0000x reference)
#include <cuda_runtime.h>
#include <cstdint>

#define BS   256
#define SEQ  512
#define H    768

// Scratch (no allocations allowed)
__device__ float g_emb[BS * H];          // gathered "embraced" rows
__device__ float g_S[3 * BS * H];        // S0 = cls@Wtop, S1 = cls@Wbot, S2 = emb@Wbot

// ---------------------------------------------------------------------------
// Threefry-2x32, 20 rounds, key = (0, 42)  (jax.random.key(42))
// PARTITIONABLE scheme (jax_threefry_partitionable=True, default since 0.4.30):
//   bits32(i) = x0 ^ x1  of  threefry2x32(key, (hi32(i), lo32(i)))
// ---------------------------------------------------------------------------
__device__ __forceinline__ uint32_t rotl32(uint32_t x, int r) {
    return (x << r) | (x >> (32 - r));
}

__device__ __forceinline__ uint32_t threefry_bits_partitionable(uint32_t i) {
    const uint32_t k0 = 0u, k1 = 42u;
    const uint32_t ks2 = 0x1BD11BDAu ^ k0 ^ k1;
    uint32_t x0 = 0u + k0;    // counter hi = 0 (n < 2^32)
    uint32_t x1 = i  + k1;    // counter lo = i

#define TF_BLOCK(r0_, r1_, r2_, r3_)                                   \
    x0 += x1; x1 = rotl32(x1, r0_); x1 ^= x0;                          \
    x0 += x1; x1 = rotl32(x1, r1_); x1 ^= x0;                          \
    x0 += x1; x1 = rotl32(x1, r2_); x1 ^= x0;                          \
    x0 += x1; x1 = rotl32(x1, r3_); x1 ^= x0;

    TF_BLOCK(13, 15, 26, 6)   x0 += k1;  x1 += ks2 + 1u;
    TF_BLOCK(17, 29, 16, 24)  x0 += ks2; x1 += k0  + 2u;
    TF_BLOCK(13, 15, 26, 6)   x0 += k0;  x1 += k1  + 3u;
    TF_BLOCK(17, 29, 16, 24)  x0 += k1;  x1 += ks2 + 4u;
    TF_BLOCK(13, 15, 26, 6)   x0 += ks2; x1 += k0  + 5u;
#undef TF_BLOCK
    return x0 ^ x1;           // 32-bit partitionable output
}

// ---------------------------------------------------------------------------
// Kernel 1: lengths (leading ones) + threefry sampling + gather of embraced
// ---------------------------------------------------------------------------
__global__ void prep_kernel(const float* __restrict__ tokens,
                            const int*   __restrict__ mask) {
    const int b = blockIdx.x;
    __shared__ int s_len;
    if (threadIdx.x == 0) s_len = SEQ;
    __syncthreads();

    // length = index of first zero (== count of leading ones)
    for (int t = threadIdx.x; t < SEQ; t += blockDim.x) {
        if (mask[b * SEQ + t] == 0) atomicMin(&s_len, t);
    }
    __syncthreads();
    const int   len  = s_len;
    const float lenf = (float)len;

    for (int j = threadIdx.x; j < H; j += blockDim.x) {
        const int i = b * H + j;          // flat index into (256,768) uniform draw
        const uint32_t bits = threefry_bits_partitionable((uint32_t)i);
        const float u = __uint_as_float((bits >> 9) | 0x3f800000u) - 1.0f;
        int idx = (int)floorf(u * lenf);
        if (idx > len - 1) idx = len - 1;       // len >= 1 always
        g_emb[i] = tokens[(size_t)b * SEQ * H + (size_t)idx * H + j];
    }
}

// ---------------------------------------------------------------------------
// Kernel 2: fp32 GEMM.  Computes g_S[g] = Xg @ Wg for g in {0,1,2}:
//   g=0: cls @ W[0:768,:]     g=1: cls @ W[768:1536,:]    g=2: emb @ W[768:1536,:]
// Tiles: BM=64, BN=64, BK=16, 256 threads, 4x4 micro-tile.
// Grid: x = 768/64 = 12, y = 3 groups * (256/64) = 12   -> 144 blocks (~1 wave)
// ---------------------------------------------------------------------------
#define BM  64
#define BN  64
#define BKC 16

__global__ void __launch_bounds__(256, 1)
gemm_kernel(const float* __restrict__ cls,
            const float* __restrict__ W) {
    const int g  = blockIdx.y >> 2;             // group 0..2
    const int m0 = (blockIdx.y & 3) * BM;       // row tile within 256 batches
    const int n0 = blockIdx.x * BN;

    const float* __restrict__ A  = (g == 2) ? g_emb : cls;
    const float* __restrict__ Wg = W + (g == 0 ? 0 : (size_t)H * H);

    __shared__ float As[BKC][BM];   // transposed: [k][m]
    __shared__ float Bs[BKC][BN];   // [k][n]

    const int tid = threadIdx.x;
    const int tm  = tid >> 4;       // 0..15
    const int tn  = tid & 15;       // 0..15

    // global-load mapping
    const int ar = tid >> 2;            // A row within tile   (0..63)
    const int ak = (tid & 3) * 4;       // A k within chunk    (0,4,8,12)
    const int wr = tid >> 4;            // W row within chunk  (0..15)
    const int wn = (tid & 15) * 4;      // W col within tile

    float acc[4][4] = {};

    for (int k0 = 0; k0 < H; k0 += BKC) {
        const float4 av = *reinterpret_cast<const float4*>(&A[(m0 + ar) * H + k0 + ak]);
        const float4 wv = *reinterpret_cast<const float4*>(&Wg[(size_t)(k0 + wr) * H + n0 + wn]);
        __syncthreads();                 // previous-iter reads done before overwrite
        As[ak + 0][ar] = av.x;
        As[ak + 1][ar] = av.y;
        As[ak + 2][ar] = av.z;
        As[ak + 3][ar] = av.w;
        *reinterpret_cast<float4*>(&Bs[wr][wn]) = wv;
        __syncthreads();

#pragma unroll
        for (int kk = 0; kk < BKC; kk++) {
            const float4 a4 = *reinterpret_cast<const float4*>(&As[kk][tm * 4]);
            const float4 b4 = *reinterpret_cast<const float4*>(&Bs[kk][tn * 4]);
            acc[0][0] += a4.x * b4.x; acc[0][1] += a4.x * b4.y; acc[0][2] += a4.x * b4.z; acc[0][3] += a4.x * b4.w;
            acc[1][0] += a4.y * b4.x; acc[1][1] += a4.y * b4.y; acc[1][2] += a4.y * b4.z; acc[1][3] += a4.y * b4.w;
            acc[2][0] += a4.z * b4.x; acc[2][1] += a4.z * b4.y; acc[2][2] += a4.z * b4.z; acc[2][3] += a4.z * b4.w;
            acc[3][0] += a4.w * b4.x; acc[3][1] += a4.w * b4.y; acc[3][2] += a4.w * b4.z; acc[3][3] += a4.w * b4.w;
        }
    }

    float* __restrict__ Cp = g_S + (size_t)g * BS * H;
#pragma unroll
    for (int r = 0; r < 4; r++) {
        float4 o = make_float4(acc[r][0], acc[r][1], acc[r][2], acc[r][3]);
        *reinterpret_cast<float4*>(&Cp[(size_t)(m0 + tm * 4 + r) * H + n0 + tn * 4]) = o;
    }
}

// ---------------------------------------------------------------------------
// Kernel 3: epilogue.  e_k = v . tanh(S0 + S_k + bias), softmax over k in {0,1},
// out = a0*cls + a1*emb.
// ---------------------------------------------------------------------------
__global__ void epilogue_kernel(const float* __restrict__ cls,
                                const float* __restrict__ bias,
                                const float* __restrict__ v,
                                float*       __restrict__ out) {
    const int b   = blockIdx.x;
    const int tid = threadIdx.x;   // 256 threads

    const float* __restrict__ S0 = g_S + (size_t)b * H;
    const float* __restrict__ S1 = g_S + (size_t)BS * H + (size_t)b * H;
    const float* __restrict__ S2 = g_S + (size_t)2 * BS * H + (size_t)b * H;

    float p0 = 0.0f, p1 = 0.0f;
    for (int j = tid; j < H; j += 256) {
        const float a  = S0[j];
        const float bb = S1[j];
        const float c  = S2[j];
        const float bi = bias[j];
        const float vv = v[j];
        p0 += tanhf(a + bb + bi) * vv;
        p1 += tanhf(a + c  + bi) * vv;
    }

    // block reduce (deterministic: fixed shuffle order + fixed smem order)
#pragma unroll
    for (int off = 16; off > 0; off >>= 1) {
        p0 += __shfl_down_sync(0xffffffffu, p0, off);
        p1 += __shfl_down_sync(0xffffffffu, p1, off);
    }
    __shared__ float r0[8], r1[8];
    __shared__ float s_alpha;
    const int w = tid >> 5, l = tid & 31;
    if (l == 0) { r0[w] = p0; r1[w] = p1; }
    __syncthreads();
    if (tid == 0) {
        float e0 = 0.0f, e1 = 0.0f;
#pragma unroll
        for (int i = 0; i < 8; i++) { e0 += r0[i]; e1 += r1[i]; }
        const float m  = fmaxf(e0, e1);
        const float w0 = expf(e0 - m);
        const float w1 = expf(e1 - m);
        s_alpha = w0 / (w0 + w1);
    }
    __syncthreads();
    const float a0 = s_alpha;
    const float a1 = 1.0f - a0;
    for (int j = tid; j < H; j += 256) {
        out[(size_t)b * H + j] = a0 * cls[(size_t)b * H + j] + a1 * g_emb[(size_t)b * H + j];
    }
}

// ---------------------------------------------------------------------------
// kernel_launch — inputs identified BY ELEMENT COUNT (robust to metadata order)
// ---------------------------------------------------------------------------
extern "C" void kernel_launch(void* const* d_in, const int* in_sizes, int n_in,
                              void* d_out, int out_size) {
    const float* tokens = nullptr;
    const float* cls    = nullptr;
    const int*   mask   = nullptr;
    const float* W      = nullptr;
    const float* bias   = nullptr;
    const float* v      = nullptr;

    for (int i = 0; i < n_in; i++) {
        const int sz = in_sizes[i];
        if      (sz == BS * SEQ * H) tokens = (const float*)d_in[i];
        else if (sz == BS * H)       cls    = (const float*)d_in[i];
        else if (sz == BS * SEQ)     mask   = (const int*)  d_in[i];
        else if (sz == 2 * H * H)    W      = (const float*)d_in[i];
        else if (sz == H) {
            if (bias == nullptr)     bias   = (const float*)d_in[i];
            else                     v      = (const float*)d_in[i];
        }
    }
    float* out = (float*)d_out;

    prep_kernel<<<BS, 256>>>(tokens, mask);
    gemm_kernel<<<dim3(H / BN, 12), 256>>>(cls, W);
    epilogue_kernel<<<BS, 256>>>(cls, bias, v, out);
}

// round 4
// speedup vs baseline: 1.2735x; 1.2735x over previous
#include <cuda_runtime.h>
#include <cstdint>

#define BS   256
#define SEQ  512
#define H    768

// Scratch (no allocations allowed)
__device__ float g_emb[BS * H];          // gathered "embraced" rows
__device__ float g_S[3 * BS * H];        // S0 = cls@Wtop, S1 = cls@Wbot, S2 = emb@Wbot
__device__ int   g_len[BS];

// ---------------------------------------------------------------------------
// Threefry-2x32, 20 rounds, key = (0, 42), partitionable scheme:
//   bits32(i) = x0 ^ x1 of threefry2x32(key, (0, i))
// ---------------------------------------------------------------------------
__device__ __forceinline__ uint32_t rotl32(uint32_t x, int r) {
    return (x << r) | (x >> (32 - r));
}

__device__ __forceinline__ uint32_t threefry_bits_partitionable(uint32_t i) {
    const uint32_t k0 = 0u, k1 = 42u;
    const uint32_t ks2 = 0x1BD11BDAu ^ k0 ^ k1;
    uint32_t x0 = 0u + k0;
    uint32_t x1 = i  + k1;

#define TF_BLOCK(r0_, r1_, r2_, r3_)                                   \
    x0 += x1; x1 = rotl32(x1, r0_); x1 ^= x0;                          \
    x0 += x1; x1 = rotl32(x1, r1_); x1 ^= x0;                          \
    x0 += x1; x1 = rotl32(x1, r2_); x1 ^= x0;                          \
    x0 += x1; x1 = rotl32(x1, r3_); x1 ^= x0;

    TF_BLOCK(13, 15, 26, 6)   x0 += k1;  x1 += ks2 + 1u;
    TF_BLOCK(17, 29, 16, 24)  x0 += ks2; x1 += k0  + 2u;
    TF_BLOCK(13, 15, 26, 6)   x0 += k0;  x1 += k1  + 3u;
    TF_BLOCK(17, 29, 16, 24)  x0 += k1;  x1 += ks2 + 4u;
    TF_BLOCK(13, 15, 26, 6)   x0 += ks2; x1 += k0  + 5u;
#undef TF_BLOCK
    return x0 ^ x1;
}

// ---------------------------------------------------------------------------
// Kernel 0: lengths. One warp per batch row; ballot scan for first zero.
// 8 blocks x 1024 threads = 256 warps.
// ---------------------------------------------------------------------------
__global__ void len_kernel(const int* __restrict__ mask) {
    const int gwarp = (blockIdx.x * blockDim.x + threadIdx.x) >> 5;  // 0..255
    const int lane  = threadIdx.x & 31;
    const int* row  = mask + gwarp * SEQ;

    int len = SEQ;
#pragma unroll
    for (int s = 0; s < SEQ / 32; s++) {
        const unsigned z = __ballot_sync(0xffffffffu, row[s * 32 + lane] == 0);
        if (z) { len = s * 32 + (__ffs(z) - 1); break; }
    }
    if (lane == 0) g_len[gwarp] = len;
}

// ---------------------------------------------------------------------------
// Kernel 1: gather. One thread per (b, j) at full occupancy.
// ---------------------------------------------------------------------------
__global__ void gather_kernel(const float* __restrict__ tokens) {
    const int i = blockIdx.x * blockDim.x + threadIdx.x;   // 0..196607
    const int b = i / H;
    const int j = i - b * H;

    const int   len  = g_len[b];
    const float lenf = (float)len;

    const uint32_t bits = threefry_bits_partitionable((uint32_t)i);
    const float u = __uint_as_float((bits >> 9) | 0x3f800000u) - 1.0f;
    int idx = (int)floorf(u * lenf);
    if (idx > len - 1) idx = len - 1;
    g_emb[i] = tokens[(size_t)b * SEQ * H + (size_t)idx * H + j];
}

// ---------------------------------------------------------------------------
// Kernel 2: TF32 tensor-core GEMM.  g_S[g] = Xg @ Wg, g in {0,1,2}.
// BM=64, BN=64, BK=16; 256 threads = 8 warps (2m x 4n), warp tile 32x16.
// mma.sync m16n8k8 tf32, fp32 accumulate. Grid (12, 12) = 144 blocks (1 wave).
// ---------------------------------------------------------------------------
#define BM   64
#define BN   64
#define BK   16
#define APAD 20   // As row stride (floats): r*20 mod 32 -> conflict-free frags
#define BPAD 72   // Bs row stride (floats): k*72 mod 32 = k*8 -> conflict-free

__device__ __forceinline__ uint32_t f2tf32(float x) {
    uint32_t y;
    asm("cvt.rna.tf32.f32 %0, %1;" : "=r"(y) : "f"(x));
    return y;
}

__device__ __forceinline__ void mma_tf32(float* d, const uint32_t* a, const uint32_t* b) {
    asm volatile(
        "mma.sync.aligned.m16n8k8.row.col.f32.tf32.tf32.f32 "
        "{%0,%1,%2,%3}, {%4,%5,%6,%7}, {%8,%9}, {%0,%1,%2,%3};\n"
        : "+f"(d[0]), "+f"(d[1]), "+f"(d[2]), "+f"(d[3])
        : "r"(a[0]), "r"(a[1]), "r"(a[2]), "r"(a[3]), "r"(b[0]), "r"(b[1]));
}

__global__ void __launch_bounds__(256, 1)
gemm_tf32_kernel(const float* __restrict__ cls,
                 const float* __restrict__ W) {
    const int g  = blockIdx.y >> 2;             // group 0..2
    const int m0 = (blockIdx.y & 3) * BM;
    const int n0 = blockIdx.x * BN;

    const float* __restrict__ A  = (g == 2) ? g_emb : cls;
    const float* __restrict__ Wg = W + (g == 0 ? 0 : (size_t)H * H);

    __shared__ uint32_t As[BM * APAD];   // [64][20]
    __shared__ uint32_t Bs[BK * BPAD];   // [16][72]

    const int tid  = threadIdx.x;
    const int warp = tid >> 5;
    const int lane = tid & 31;
    const int wm   = (warp & 1) * 32;    // warp m offset: 0 / 32
    const int wn   = (warp >> 1) * 16;   // warp n offset: 0 / 16 / 32 / 48

    const int grp = lane >> 2;           // 0..7
    const int tig = lane & 3;            // 0..3

    // staging mapping
    const int a_r = tid >> 2;            // 0..63
    const int a_c = (tid & 3) * 4;       // 0,4,8,12
    const int b_r = tid >> 4;            // 0..15
    const int b_c = (tid & 15) * 4;      // 0..60

    float acc[2][2][4];
#pragma unroll
    for (int mi = 0; mi < 2; mi++)
#pragma unroll
        for (int ni = 0; ni < 2; ni++)
#pragma unroll
            for (int r = 0; r < 4; r++) acc[mi][ni][r] = 0.0f;

    for (int k0 = 0; k0 < H; k0 += BK) {
        const float4 av = *reinterpret_cast<const float4*>(&A[(m0 + a_r) * H + k0 + a_c]);
        const float4 bv = *reinterpret_cast<const float4*>(&Wg[(size_t)(k0 + b_r) * H + n0 + b_c]);
        __syncthreads();
        uint4 at = make_uint4(f2tf32(av.x), f2tf32(av.y), f2tf32(av.z), f2tf32(av.w));
        uint4 bt = make_uint4(f2tf32(bv.x), f2tf32(bv.y), f2tf32(bv.z), f2tf32(bv.w));
        *reinterpret_cast<uint4*>(&As[a_r * APAD + a_c]) = at;
        *reinterpret_cast<uint4*>(&Bs[b_r * BPAD + b_c]) = bt;
        __syncthreads();

#pragma unroll
        for (int ks = 0; ks < BK; ks += 8) {
            uint32_t afr[2][4];
#pragma unroll
            for (int mi = 0; mi < 2; mi++) {
                const int rbase = (wm + mi * 16 + grp) * APAD + ks + tig;
                afr[mi][0] = As[rbase];
                afr[mi][1] = As[rbase + 8 * APAD];
                afr[mi][2] = As[rbase + 4];
                afr[mi][3] = As[rbase + 8 * APAD + 4];
            }
            uint32_t bfr[2][2];
#pragma unroll
            for (int ni = 0; ni < 2; ni++) {
                const int cbase = (ks + tig) * BPAD + wn + ni * 8 + grp;
                bfr[ni][0] = Bs[cbase];
                bfr[ni][1] = Bs[cbase + 4 * BPAD];
            }
#pragma unroll
            for (int mi = 0; mi < 2; mi++)
#pragma unroll
                for (int ni = 0; ni < 2; ni++)
                    mma_tf32(acc[mi][ni], afr[mi], bfr[ni]);
        }
    }

    // write-out: warp tile rows m0+wm+mi*16+{grp, grp+8}, cols n0+wn+ni*8+tig*2
    float* __restrict__ Cp = g_S + (size_t)g * BS * H;
#pragma unroll
    for (int mi = 0; mi < 2; mi++) {
#pragma unroll
        for (int ni = 0; ni < 2; ni++) {
            const int col = n0 + wn + ni * 8 + tig * 2;
            const int r0  = m0 + wm + mi * 16 + grp;
            *reinterpret_cast<float2*>(&Cp[(size_t)r0 * H + col]) =
                make_float2(acc[mi][ni][0], acc[mi][ni][1]);
            *reinterpret_cast<float2*>(&Cp[(size_t)(r0 + 8) * H + col]) =
                make_float2(acc[mi][ni][2], acc[mi][ni][3]);
        }
    }
}

// ---------------------------------------------------------------------------
// Kernel 3: epilogue.  e_k = v . tanh(S0 + S_k + bias), softmax over {0,1},
// out = a0*cls + a1*emb.
// ---------------------------------------------------------------------------
__global__ void epilogue_kernel(const float* __restrict__ cls,
                                const float* __restrict__ bias,
                                const float* __restrict__ v,
                                float*       __restrict__ out) {
    const int b   = blockIdx.x;
    const int tid = threadIdx.x;   // 256 threads

    const float* __restrict__ S0 = g_S + (size_t)b * H;
    const float* __restrict__ S1 = g_S + (size_t)BS * H + (size_t)b * H;
    const float* __restrict__ S2 = g_S + (size_t)2 * BS * H + (size_t)b * H;

    float p0 = 0.0f, p1 = 0.0f;
    for (int j = tid; j < H; j += 256) {
        const float a  = S0[j];
        const float bb = S1[j];
        const float c  = S2[j];
        const float bi = bias[j];
        const float vv = v[j];
        p0 += tanhf(a + bb + bi) * vv;
        p1 += tanhf(a + c  + bi) * vv;
    }

#pragma unroll
    for (int off = 16; off > 0; off >>= 1) {
        p0 += __shfl_down_sync(0xffffffffu, p0, off);
        p1 += __shfl_down_sync(0xffffffffu, p1, off);
    }
    __shared__ float r0[8], r1[8];
    __shared__ float s_alpha;
    const int w = tid >> 5, l = tid & 31;
    if (l == 0) { r0[w] = p0; r1[w] = p1; }
    __syncthreads();
    if (tid == 0) {
        float e0 = 0.0f, e1 = 0.0f;
#pragma unroll
        for (int i = 0; i < 8; i++) { e0 += r0[i]; e1 += r1[i]; }
        const float m  = fmaxf(e0, e1);
        const float w0 = expf(e0 - m);
        const float w1 = expf(e1 - m);
        s_alpha = w0 / (w0 + w1);
    }
    __syncthreads();
    const float a0 = s_alpha;
    const float a1 = 1.0f - a0;
    for (int j = tid; j < H; j += 256) {
        out[(size_t)b * H + j] = a0 * cls[(size_t)b * H + j] + a1 * g_emb[(size_t)b * H + j];
    }
}

// ---------------------------------------------------------------------------
// kernel_launch — inputs identified BY ELEMENT COUNT
// ---------------------------------------------------------------------------
extern "C" void kernel_launch(void* const* d_in, const int* in_sizes, int n_in,
                              void* d_out, int out_size) {
    const float* tokens = nullptr;
    const float* cls    = nullptr;
    const int*   mask   = nullptr;
    const float* W      = nullptr;
    const float* bias   = nullptr;
    const float* v      = nullptr;

    for (int i = 0; i < n_in; i++) {
        const int sz = in_sizes[i];
        if      (sz == BS * SEQ * H) tokens = (const float*)d_in[i];
        else if (sz == BS * H)       cls    = (const float*)d_in[i];
        else if (sz == BS * SEQ)     mask   = (const int*)  d_in[i];
        else if (sz == 2 * H * H)    W      = (const float*)d_in[i];
        else if (sz == H) {
            if (bias == nullptr)     bias   = (const float*)d_in[i];
            else                     v      = (const float*)d_in[i];
        }
    }
    float* out = (float*)d_out;

    len_kernel<<<8, 1024>>>(mask);
    gather_kernel<<<(BS * H) / 512, 512>>>(tokens);
    gemm_tf32_kernel<<<dim3(H / BN, 12), 256>>>(cls, W);
    epilogue_kernel<<<BS, 256>>>(cls, bias, v, out);
}

// round 5
// speedup vs baseline: 1.7372x; 1.3641x over previous
#include <cuda_runtime.h>
#include <cstdint>

#define BS   256
#define SEQ  512
#define H    768

// Scratch (no allocations allowed)
__device__ float g_emb[BS * H];          // gathered "embraced" rows
__device__ float g_S[3 * BS * H];        // S0 = cls@Wtop, S1 = cls@Wbot, S2 = emb@Wbot

// ---------------------------------------------------------------------------
// Threefry-2x32, 20 rounds, key = (0, 42), partitionable scheme:
//   bits32(i) = x0 ^ x1 of threefry2x32(key, (0, i))
// ---------------------------------------------------------------------------
__device__ __forceinline__ uint32_t rotl32(uint32_t x, int r) {
    return (x << r) | (x >> (32 - r));
}

__device__ __forceinline__ uint32_t threefry_bits_partitionable(uint32_t i) {
    const uint32_t k0 = 0u, k1 = 42u;
    const uint32_t ks2 = 0x1BD11BDAu ^ k0 ^ k1;
    uint32_t x0 = 0u + k0;
    uint32_t x1 = i  + k1;

#define TF_BLOCK(r0_, r1_, r2_, r3_)                                   \
    x0 += x1; x1 = rotl32(x1, r0_); x1 ^= x0;                          \
    x0 += x1; x1 = rotl32(x1, r1_); x1 ^= x0;                          \
    x0 += x1; x1 = rotl32(x1, r2_); x1 ^= x0;                          \
    x0 += x1; x1 = rotl32(x1, r3_); x1 ^= x0;

    TF_BLOCK(13, 15, 26, 6)   x0 += k1;  x1 += ks2 + 1u;
    TF_BLOCK(17, 29, 16, 24)  x0 += ks2; x1 += k0  + 2u;
    TF_BLOCK(13, 15, 26, 6)   x0 += k0;  x1 += k1  + 3u;
    TF_BLOCK(17, 29, 16, 24)  x0 += k1;  x1 += ks2 + 4u;
    TF_BLOCK(13, 15, 26, 6)   x0 += ks2; x1 += k0  + 5u;
#undef TF_BLOCK
    return x0 ^ x1;
}

// ---------------------------------------------------------------------------
// Kernel 1: fused length + threefry sampling + gather. Block per batch, 768 thr.
// ---------------------------------------------------------------------------
__global__ void __launch_bounds__(768, 2)
prep_kernel(const float* __restrict__ tokens,
            const int*   __restrict__ mask) {
    const int b   = blockIdx.x;
    const int tid = threadIdx.x;
    __shared__ int s_len;
    if (tid == 0) s_len = SEQ;
    __syncthreads();

    if (tid < SEQ && mask[b * SEQ + tid] == 0) atomicMin(&s_len, tid);
    __syncthreads();
    const int   len  = s_len;
    const float lenf = (float)len;

    const int i = b * H + tid;
    const uint32_t bits = threefry_bits_partitionable((uint32_t)i);
    const float u = __uint_as_float((bits >> 9) | 0x3f800000u) - 1.0f;
    int idx = (int)floorf(u * lenf);
    if (idx > len - 1) idx = len - 1;
    g_emb[i] = tokens[(size_t)b * SEQ * H + (size_t)idx * H + tid];
}

// ---------------------------------------------------------------------------
// Kernel 2: TF32 tensor-core GEMM, double-buffered smem.
// g_S[g] = Xg @ Wg, g in {0,1,2}. BM=64, BN=64, BK=16; 256 threads = 8 warps,
// warp tile 32x16. Grid (12, 12) = 144 blocks (1 wave).
// ---------------------------------------------------------------------------
#define BM   64
#define BN   64
#define BK   16
#define NIT  (H / BK)   // 48
#define APAD 20   // As row stride (uint32): conflict-free frag reads
#define BPAD 72   // Bs row stride (uint32): conflict-free frag reads

__device__ __forceinline__ uint32_t f2tf32(float x) {
    uint32_t y;
    asm("cvt.rna.tf32.f32 %0, %1;" : "=r"(y) : "f"(x));
    return y;
}

__device__ __forceinline__ void mma_tf32(float* d, const uint32_t* a, const uint32_t* b) {
    asm volatile(
        "mma.sync.aligned.m16n8k8.row.col.f32.tf32.tf32.f32 "
        "{%0,%1,%2,%3}, {%4,%5,%6,%7}, {%8,%9}, {%0,%1,%2,%3};\n"
        : "+f"(d[0]), "+f"(d[1]), "+f"(d[2]), "+f"(d[3])
        : "r"(a[0]), "r"(a[1]), "r"(a[2]), "r"(a[3]), "r"(b[0]), "r"(b[1]));
}

__device__ __forceinline__ void compute_tile(const uint32_t* __restrict__ As,
                                             const uint32_t* __restrict__ Bs,
                                             int wm, int wn, int grp, int tig,
                                             float acc[2][2][4]) {
#pragma unroll
    for (int ks = 0; ks < BK; ks += 8) {
        uint32_t afr[2][4];
#pragma unroll
        for (int mi = 0; mi < 2; mi++) {
            const int rbase = (wm + mi * 16 + grp) * APAD + ks + tig;
            afr[mi][0] = As[rbase];
            afr[mi][1] = As[rbase + 8 * APAD];
            afr[mi][2] = As[rbase + 4];
            afr[mi][3] = As[rbase + 8 * APAD + 4];
        }
        uint32_t bfr[2][2];
#pragma unroll
        for (int ni = 0; ni < 2; ni++) {
            const int cbase = (ks + tig) * BPAD + wn + ni * 8 + grp;
            bfr[ni][0] = Bs[cbase];
            bfr[ni][1] = Bs[cbase + 4 * BPAD];
        }
#pragma unroll
        for (int mi = 0; mi < 2; mi++)
#pragma unroll
            for (int ni = 0; ni < 2; ni++)
                mma_tf32(acc[mi][ni], afr[mi], bfr[ni]);
    }
}

__global__ void __launch_bounds__(256, 1)
gemm_tf32_kernel(const float* __restrict__ cls,
                 const float* __restrict__ W) {
    const int g  = blockIdx.y >> 2;             // group 0..2
    const int m0 = (blockIdx.y & 3) * BM;
    const int n0 = blockIdx.x * BN;

    const float* __restrict__ A  = (g == 2) ? g_emb : cls;
    const float* __restrict__ Wg = W + (g == 0 ? 0 : (size_t)H * H);

    __shared__ uint32_t As[2][BM * APAD];
    __shared__ uint32_t Bs[2][BK * BPAD];

    const int tid  = threadIdx.x;
    const int warp = tid >> 5;
    const int lane = tid & 31;
    const int wm   = (warp & 1) * 32;
    const int wn   = (warp >> 1) * 16;
    const int grp  = lane >> 2;
    const int tig  = lane & 3;

    // staging mapping
    const int a_r = tid >> 2;            // 0..63
    const int a_c = (tid & 3) * 4;       // 0,4,8,12
    const int b_r = tid >> 4;            // 0..15
    const int b_c = (tid & 15) * 4;      // 0..60

    const float* a_src = &A[(m0 + a_r) * H + a_c];
    const float* b_src = &Wg[(size_t)b_r * H + n0 + b_c];

    float acc[2][2][4];
#pragma unroll
    for (int mi = 0; mi < 2; mi++)
#pragma unroll
        for (int ni = 0; ni < 2; ni++)
#pragma unroll
            for (int r = 0; r < 4; r++) acc[mi][ni][r] = 0.0f;

    // prologue: stage tile 0
    {
        const float4 av = *reinterpret_cast<const float4*>(a_src);
        const float4 bv = *reinterpret_cast<const float4*>(b_src);
        *reinterpret_cast<uint4*>(&As[0][a_r * APAD + a_c]) =
            make_uint4(f2tf32(av.x), f2tf32(av.y), f2tf32(av.z), f2tf32(av.w));
        *reinterpret_cast<uint4*>(&Bs[0][b_r * BPAD + b_c]) =
            make_uint4(f2tf32(bv.x), f2tf32(bv.y), f2tf32(bv.z), f2tf32(bv.w));
    }
    __syncthreads();

    for (int it = 1; it < NIT; it++) {
        const int k0 = it * BK;
        // issue next tile's global loads first (latency overlapped with compute)
        const float4 av = *reinterpret_cast<const float4*>(a_src + k0);
        const float4 bv = *reinterpret_cast<const float4*>(b_src + (size_t)k0 * H);

        compute_tile(As[(it - 1) & 1], Bs[(it - 1) & 1], wm, wn, grp, tig, acc);

        *reinterpret_cast<uint4*>(&As[it & 1][a_r * APAD + a_c]) =
            make_uint4(f2tf32(av.x), f2tf32(av.y), f2tf32(av.z), f2tf32(av.w));
        *reinterpret_cast<uint4*>(&Bs[it & 1][b_r * BPAD + b_c]) =
            make_uint4(f2tf32(bv.x), f2tf32(bv.y), f2tf32(bv.z), f2tf32(bv.w));
        __syncthreads();
    }
    compute_tile(As[(NIT - 1) & 1], Bs[(NIT - 1) & 1], wm, wn, grp, tig, acc);

    float* __restrict__ Cp = g_S + (size_t)g * BS * H;
#pragma unroll
    for (int mi = 0; mi < 2; mi++) {
#pragma unroll
        for (int ni = 0; ni < 2; ni++) {
            const int col = n0 + wn + ni * 8 + tig * 2;
            const int r0  = m0 + wm + mi * 16 + grp;
            *reinterpret_cast<float2*>(&Cp[(size_t)r0 * H + col]) =
                make_float2(acc[mi][ni][0], acc[mi][ni][1]);
            *reinterpret_cast<float2*>(&Cp[(size_t)(r0 + 8) * H + col]) =
                make_float2(acc[mi][ni][2], acc[mi][ni][3]);
        }
    }
}

// ---------------------------------------------------------------------------
// Kernel 3: epilogue. 768 threads/block, one thread per (b, j).
// e_k = v . tanh(S0 + S_k + bias), softmax over {0,1}, out = a0*cls + a1*emb.
// ---------------------------------------------------------------------------
__global__ void __launch_bounds__(768, 2)
epilogue_kernel(const float* __restrict__ cls,
                const float* __restrict__ bias,
                const float* __restrict__ v,
                float*       __restrict__ out) {
    const int b   = blockIdx.x;
    const int tid = threadIdx.x;   // 0..767

    const size_t base = (size_t)b * H + tid;
    const float a  = g_S[base];
    const float bb = g_S[(size_t)BS * H + base];
    const float c  = g_S[(size_t)2 * BS * H + base];
    const float bi = bias[tid];
    const float vv = v[tid];

    float p0 = tanhf(a + bb + bi) * vv;
    float p1 = tanhf(a + c  + bi) * vv;

    // block reduce: 24 warps (deterministic fixed order)
#pragma unroll
    for (int off = 16; off > 0; off >>= 1) {
        p0 += __shfl_down_sync(0xffffffffu, p0, off);
        p1 += __shfl_down_sync(0xffffffffu, p1, off);
    }
    __shared__ float r0[24], r1[24];
    __shared__ float s_alpha;
    const int w = tid >> 5, l = tid & 31;
    if (l == 0) { r0[w] = p0; r1[w] = p1; }
    __syncthreads();
    if (tid == 0) {
        float e0 = 0.0f, e1 = 0.0f;
#pragma unroll
        for (int i = 0; i < 24; i++) { e0 += r0[i]; e1 += r1[i]; }
        const float m  = fmaxf(e0, e1);
        const float w0 = expf(e0 - m);
        const float w1 = expf(e1 - m);
        s_alpha = w0 / (w0 + w1);
    }
    __syncthreads();
    const float a0 = s_alpha;
    out[base] = a0 * cls[base] + (1.0f - a0) * g_emb[base];
}

// ---------------------------------------------------------------------------
// kernel_launch — inputs identified BY ELEMENT COUNT
// ---------------------------------------------------------------------------
extern "C" void kernel_launch(void* const* d_in, const int* in_sizes, int n_in,
                              void* d_out, int out_size) {
    const float* tokens = nullptr;
    const float* cls    = nullptr;
    const int*   mask   = nullptr;
    const float* W      = nullptr;
    const float* bias   = nullptr;
    const float* v      = nullptr;

    for (int i = 0; i < n_in; i++) {
        const int sz = in_sizes[i];
        if      (sz == BS * SEQ * H) tokens = (const float*)d_in[i];
        else if (sz == BS * H)       cls    = (const float*)d_in[i];
        else if (sz == BS * SEQ)     mask   = (const int*)  d_in[i];
        else if (sz == 2 * H * H)    W      = (const float*)d_in[i];
        else if (sz == H) {
            if (bias == nullptr)     bias   = (const float*)d_in[i];
            else                     v      = (const float*)d_in[i];
        }
    }
    float* out = (float*)d_out;

    prep_kernel<<<BS, 768>>>(tokens, mask);
    gemm_tf32_kernel<<<dim3(H / BN, 12), 256>>>(cls, W);
    epilogue_kernel<<<BS, 768>>>(cls, bias, v, out);
}

// round 6
// speedup vs baseline: 1.8418x; 1.0602x over previous
#include <cuda_runtime.h>
#include <cstdint>

#define BS   256
#define SEQ  512
#define H    768

// Scratch (no allocations allowed)
__device__ float g_emb[BS * H];          // gathered "embraced" rows
__device__ float g_S[3 * BS * H];        // S0 = cls@Wtop, S1 = cls@Wbot, S2 = emb@Wbot
__device__ int   g_len[BS];

// ---------------------------------------------------------------------------
// Threefry-2x32, 20 rounds, key = (0, 42), partitionable scheme:
//   bits32(i) = x0 ^ x1 of threefry2x32(key, (0, i))
// ---------------------------------------------------------------------------
__device__ __forceinline__ uint32_t rotl32(uint32_t x, int r) {
    return (x << r) | (x >> (32 - r));
}

__device__ __forceinline__ uint32_t threefry_bits_partitionable(uint32_t i) {
    const uint32_t k0 = 0u, k1 = 42u;
    const uint32_t ks2 = 0x1BD11BDAu ^ k0 ^ k1;
    uint32_t x0 = 0u + k0;
    uint32_t x1 = i  + k1;

#define TF_BLOCK(r0_, r1_, r2_, r3_)                                   \
    x0 += x1; x1 = rotl32(x1, r0_); x1 ^= x0;                          \
    x0 += x1; x1 = rotl32(x1, r1_); x1 ^= x0;                          \
    x0 += x1; x1 = rotl32(x1, r2_); x1 ^= x0;                          \
    x0 += x1; x1 = rotl32(x1, r3_); x1 ^= x0;

    TF_BLOCK(13, 15, 26, 6)   x0 += k1;  x1 += ks2 + 1u;
    TF_BLOCK(17, 29, 16, 24)  x0 += ks2; x1 += k0  + 2u;
    TF_BLOCK(13, 15, 26, 6)   x0 += k0;  x1 += k1  + 3u;
    TF_BLOCK(17, 29, 16, 24)  x0 += k1;  x1 += ks2 + 4u;
    TF_BLOCK(13, 15, 26, 6)   x0 += ks2; x1 += k0  + 5u;
#undef TF_BLOCK
    return x0 ^ x1;
}

// ---------------------------------------------------------------------------
// Kernel 0: lengths. One warp per batch row; ballot scan for first zero.
// ---------------------------------------------------------------------------
__global__ void len_kernel(const int* __restrict__ mask) {
    const int gwarp = (blockIdx.x * blockDim.x + threadIdx.x) >> 5;  // 0..255
    const int lane  = threadIdx.x & 31;
    const int* row  = mask + gwarp * SEQ;

    int len = SEQ;
#pragma unroll
    for (int s = 0; s < SEQ / 32; s++) {
        const unsigned z = __ballot_sync(0xffffffffu, row[s * 32 + lane] == 0);
        if (z) { len = s * 32 + (__ffs(z) - 1); break; }
    }
    if (lane == 0) g_len[gwarp] = len;
}

// ---------------------------------------------------------------------------
// Kernel 1: gather, 2 elements/thread, L2-only (sector-granular) loads.
// ---------------------------------------------------------------------------
__global__ void gather_kernel(const float* __restrict__ tokens) {
    const int t  = blockIdx.x * blockDim.x + threadIdx.x;   // 0..98303
    const int i0 = t * 2;                                   // even, pair in same row
    const int b  = i0 / H;
    const int j0 = i0 - b * H;

    const int   len  = g_len[b];
    const float lenf = (float)len;

    const uint32_t bits0 = threefry_bits_partitionable((uint32_t)i0);
    const uint32_t bits1 = threefry_bits_partitionable((uint32_t)(i0 + 1));
    const float u0 = __uint_as_float((bits0 >> 9) | 0x3f800000u) - 1.0f;
    const float u1 = __uint_as_float((bits1 >> 9) | 0x3f800000u) - 1.0f;
    int idx0 = (int)floorf(u0 * lenf);
    int idx1 = (int)floorf(u1 * lenf);
    if (idx0 > len - 1) idx0 = len - 1;
    if (idx1 > len - 1) idx1 = len - 1;

    const size_t rowb = (size_t)b * SEQ * H;
    const float e0 = __ldcg(&tokens[rowb + (size_t)idx0 * H + j0]);
    const float e1 = __ldcg(&tokens[rowb + (size_t)idx1 * H + j0 + 1]);
    *reinterpret_cast<float2*>(&g_emb[i0]) = make_float2(e0, e1);
}

// ---------------------------------------------------------------------------
// Kernel 2: TF32 tensor-core GEMM, 4-stage cp.async pipeline.
// Raw f32 bits fed to mma.tf32 (HW reads top 19 bits = tf32 truncation).
// g_S[g] = Xg @ Wg, g in {0,1,2}. BM=64, BN=64, BK=16; 256 threads = 8 warps,
// warp tile 32x16. Grid (12, 12) = 144 blocks (1 wave).
// ---------------------------------------------------------------------------
#define BM     64
#define BN     64
#define BK     16
#define NIT    (H / BK)   // 48
#define NSTAGE 4
#define APAD   20   // As row stride (words): conflict-free frag reads
#define BPAD   72   // Bs row stride (words): conflict-free frag reads
#define A_WORDS (BM * APAD)   // 1280
#define B_WORDS (BK * BPAD)   // 1152

__device__ __forceinline__ void cp16(uint32_t saddr, const void* gaddr) {
    asm volatile("cp.async.ca.shared.global [%0], [%1], 16;\n"
                 :: "r"(saddr), "l"(gaddr));
}
__device__ __forceinline__ void cp_commit() {
    asm volatile("cp.async.commit_group;\n");
}
template <int N>
__device__ __forceinline__ void cp_wait() {
    asm volatile("cp.async.wait_group %0;\n" :: "n"(N));
}

__device__ __forceinline__ void mma_tf32(float* d, const uint32_t* a, const uint32_t* b) {
    asm volatile(
        "mma.sync.aligned.m16n8k8.row.col.f32.tf32.tf32.f32 "
        "{%0,%1,%2,%3}, {%4,%5,%6,%7}, {%8,%9}, {%0,%1,%2,%3};\n"
        : "+f"(d[0]), "+f"(d[1]), "+f"(d[2]), "+f"(d[3])
        : "r"(a[0]), "r"(a[1]), "r"(a[2]), "r"(a[3]), "r"(b[0]), "r"(b[1]));
}

__device__ __forceinline__ void compute_tile(const uint32_t* __restrict__ As,
                                             const uint32_t* __restrict__ Bs,
                                             int wm, int wn, int grp, int tig,
                                             float acc[2][2][4]) {
#pragma unroll
    for (int ks = 0; ks < BK; ks += 8) {
        uint32_t afr[2][4];
#pragma unroll
        for (int mi = 0; mi < 2; mi++) {
            const int rbase = (wm + mi * 16 + grp) * APAD + ks + tig;
            afr[mi][0] = As[rbase];
            afr[mi][1] = As[rbase + 8 * APAD];
            afr[mi][2] = As[rbase + 4];
            afr[mi][3] = As[rbase + 8 * APAD + 4];
        }
        uint32_t bfr[2][2];
#pragma unroll
        for (int ni = 0; ni < 2; ni++) {
            const int cbase = (ks + tig) * BPAD + wn + ni * 8 + grp;
            bfr[ni][0] = Bs[cbase];
            bfr[ni][1] = Bs[cbase + 4 * BPAD];
        }
#pragma unroll
        for (int mi = 0; mi < 2; mi++)
#pragma unroll
            for (int ni = 0; ni < 2; ni++)
                mma_tf32(acc[mi][ni], afr[mi], bfr[ni]);
    }
}

__global__ void __launch_bounds__(256, 1)
gemm_tf32_kernel(const float* __restrict__ cls,
                 const float* __restrict__ W) {
    const int g  = blockIdx.y >> 2;             // group 0..2
    const int m0 = (blockIdx.y & 3) * BM;
    const int n0 = blockIdx.x * BN;

    const float* __restrict__ A  = (g == 2) ? g_emb : cls;
    const float* __restrict__ Wg = W + (g == 0 ? 0 : (size_t)H * H);

    __shared__ uint32_t As[NSTAGE][A_WORDS];
    __shared__ uint32_t Bs[NSTAGE][B_WORDS];

    const int tid  = threadIdx.x;
    const int warp = tid >> 5;
    const int lane = tid & 31;
    const int wm   = (warp & 1) * 32;
    const int wn   = (warp >> 1) * 16;
    const int grp  = lane >> 2;
    const int tig  = lane & 3;

    // staging mapping (one A float4 + one B float4 per thread per stage)
    const int a_r = tid >> 2;            // 0..63
    const int a_c = (tid & 3) * 4;       // 0,4,8,12
    const int b_r = tid >> 4;            // 0..15
    const int b_c = (tid & 15) * 4;      // 0..60

    const float* a_src = &A[(m0 + a_r) * H + a_c];
    const float* b_src = &Wg[(size_t)b_r * H + n0 + b_c];

    const uint32_t s_as = (uint32_t)__cvta_generic_to_shared(&As[0][0]) +
                          (uint32_t)((a_r * APAD + a_c) * 4);
    const uint32_t s_bs = (uint32_t)__cvta_generic_to_shared(&Bs[0][0]) +
                          (uint32_t)((b_r * BPAD + b_c) * 4);

    float acc[2][2][4];
#pragma unroll
    for (int mi = 0; mi < 2; mi++)
#pragma unroll
        for (int ni = 0; ni < 2; ni++)
#pragma unroll
            for (int r = 0; r < 4; r++) acc[mi][ni][r] = 0.0f;

    // prologue: issue stages 0..2
#pragma unroll
    for (int s = 0; s < NSTAGE - 1; s++) {
        cp16(s_as + (uint32_t)(s * A_WORDS * 4), a_src + s * BK);
        cp16(s_bs + (uint32_t)(s * B_WORDS * 4), b_src + (size_t)(s * BK) * H);
        cp_commit();
    }

    for (int it = 0; it < NIT; it++) {
        cp_wait<NSTAGE - 2>();           // tile `it` resident
        __syncthreads();                 // visible to all warps; prev compute done

        const int nx = it + NSTAGE - 1;
        if (nx < NIT) {
            const int buf = nx & (NSTAGE - 1);
            cp16(s_as + (uint32_t)(buf * A_WORDS * 4), a_src + nx * BK);
            cp16(s_bs + (uint32_t)(buf * B_WORDS * 4), b_src + (size_t)(nx * BK) * H);
        }
        cp_commit();                     // commit (possibly empty) to keep counts aligned

        compute_tile(As[it & (NSTAGE - 1)], Bs[it & (NSTAGE - 1)],
                     wm, wn, grp, tig, acc);
    }

    float* __restrict__ Cp = g_S + (size_t)g * BS * H;
#pragma unroll
    for (int mi = 0; mi < 2; mi++) {
#pragma unroll
        for (int ni = 0; ni < 2; ni++) {
            const int col = n0 + wn + ni * 8 + tig * 2;
            const int r0  = m0 + wm + mi * 16 + grp;
            *reinterpret_cast<float2*>(&Cp[(size_t)r0 * H + col]) =
                make_float2(acc[mi][ni][0], acc[mi][ni][1]);
            *reinterpret_cast<float2*>(&Cp[(size_t)(r0 + 8) * H + col]) =
                make_float2(acc[mi][ni][2], acc[mi][ni][3]);
        }
    }
}

// ---------------------------------------------------------------------------
// Kernel 3: epilogue. 768 threads/block, one thread per (b, j).
// e_k = v . tanh(S0 + S_k + bias), softmax over {0,1}, out = a0*cls + a1*emb.
// ---------------------------------------------------------------------------
__global__ void __launch_bounds__(768, 2)
epilogue_kernel(const float* __restrict__ cls,
                const float* __restrict__ bias,
                const float* __restrict__ v,
                float*       __restrict__ out) {
    const int b   = blockIdx.x;
    const int tid = threadIdx.x;   // 0..767

    const size_t base = (size_t)b * H + tid;
    const float a  = g_S[base];
    const float bb = g_S[(size_t)BS * H + base];
    const float c  = g_S[(size_t)2 * BS * H + base];
    const float bi = bias[tid];
    const float vv = v[tid];

    float p0 = tanhf(a + bb + bi) * vv;
    float p1 = tanhf(a + c  + bi) * vv;

#pragma unroll
    for (int off = 16; off > 0; off >>= 1) {
        p0 += __shfl_down_sync(0xffffffffu, p0, off);
        p1 += __shfl_down_sync(0xffffffffu, p1, off);
    }
    __shared__ float r0[24], r1[24];
    __shared__ float s_alpha;
    const int w = tid >> 5, l = tid & 31;
    if (l == 0) { r0[w] = p0; r1[w] = p1; }
    __syncthreads();
    if (tid == 0) {
        float e0 = 0.0f, e1 = 0.0f;
#pragma unroll
        for (int i = 0; i < 24; i++) { e0 += r0[i]; e1 += r1[i]; }
        const float m  = fmaxf(e0, e1);
        const float w0 = expf(e0 - m);
        const float w1 = expf(e1 - m);
        s_alpha = w0 / (w0 + w1);
    }
    __syncthreads();
    const float a0 = s_alpha;
    out[base] = a0 * cls[base] + (1.0f - a0) * g_emb[base];
}

// ---------------------------------------------------------------------------
// kernel_launch — inputs identified BY ELEMENT COUNT
// ---------------------------------------------------------------------------
extern "C" void kernel_launch(void* const* d_in, const int* in_sizes, int n_in,
                              void* d_out, int out_size) {
    const float* tokens = nullptr;
    const float* cls    = nullptr;
    const int*   mask   = nullptr;
    const float* W      = nullptr;
    const float* bias   = nullptr;
    const float* v      = nullptr;

    for (int i = 0; i < n_in; i++) {
        const int sz = in_sizes[i];
        if      (sz == BS * SEQ * H) tokens = (const float*)d_in[i];
        else if (sz == BS * H)       cls    = (const float*)d_in[i];
        else if (sz == BS * SEQ)     mask   = (const int*)  d_in[i];
        else if (sz == 2 * H * H)    W      = (const float*)d_in[i];
        else if (sz == H) {
            if (bias == nullptr)     bias   = (const float*)d_in[i];
            else                     v      = (const float*)d_in[i];
        }
    }
    float* out = (float*)d_out;

    len_kernel<<<8, 1024>>>(mask);
    gather_kernel<<<(BS * H / 2) / 1024, 1024>>>(tokens);
    gemm_tf32_kernel<<<dim3(H / BN, 12), 256>>>(cls, W);
    epilogue_kernel<<<BS, 768>>>(cls, bias, v, out);
}

// round 7
// speedup vs baseline: 2.1458x; 1.1651x over previous
#include <cuda_runtime.h>
#include <cstdint>

#define BS   256
#define SEQ  512
#define H    768

// Scratch (no allocations allowed)
__device__ float g_emb[BS * H];          // gathered "embraced" rows
__device__ float g_S[3 * BS * H];        // S0 = cls@Wtop, S1 = cls@Wbot, S2 = emb@Wbot
__device__ float g_alpha[BS];

// ---------------------------------------------------------------------------
// Threefry-2x32, 20 rounds, key = (0, 42), partitionable scheme:
//   bits32(i) = x0 ^ x1 of threefry2x32(key, (0, i))
// ---------------------------------------------------------------------------
__device__ __forceinline__ uint32_t rotl32(uint32_t x, int r) {
    return (x << r) | (x >> (32 - r));
}

__device__ __forceinline__ uint32_t threefry_bits_partitionable(uint32_t i) {
    const uint32_t k0 = 0u, k1 = 42u;
    const uint32_t ks2 = 0x1BD11BDAu ^ k0 ^ k1;
    uint32_t x0 = 0u + k0;
    uint32_t x1 = i  + k1;

#define TF_BLOCK(r0_, r1_, r2_, r3_)                                   \
    x0 += x1; x1 = rotl32(x1, r0_); x1 ^= x0;                          \
    x0 += x1; x1 = rotl32(x1, r1_); x1 ^= x0;                          \
    x0 += x1; x1 = rotl32(x1, r2_); x1 ^= x0;                          \
    x0 += x1; x1 = rotl32(x1, r3_); x1 ^= x0;

    TF_BLOCK(13, 15, 26, 6)   x0 += k1;  x1 += ks2 + 1u;
    TF_BLOCK(17, 29, 16, 24)  x0 += ks2; x1 += k0  + 2u;
    TF_BLOCK(13, 15, 26, 6)   x0 += k0;  x1 += k1  + 3u;
    TF_BLOCK(17, 29, 16, 24)  x0 += k1;  x1 += ks2 + 4u;
    TF_BLOCK(13, 15, 26, 6)   x0 += ks2; x1 += k0  + 5u;
#undef TF_BLOCK
    return x0 ^ x1;
}

// ---------------------------------------------------------------------------
// Kernel 1: fused length-scan + gather. One block per batch, 384 threads,
// 2 elements per thread, L2-only (sector-granular) gather loads.
// ---------------------------------------------------------------------------
__global__ void __launch_bounds__(384, 4)
prep_kernel(const float* __restrict__ tokens,
            const int*   __restrict__ mask) {
    const int b   = blockIdx.x;
    const int tid = threadIdx.x;   // 0..383

    __shared__ int s_len;
    if (tid == 0) s_len = SEQ;
    __syncthreads();
    // scan mask[b][0..511] with 384 threads (2 strided checks each)
    if (mask[b * SEQ + tid] == 0) atomicMin(&s_len, tid);
    {
        const int t2 = tid + 384;
        if (t2 < SEQ && mask[b * SEQ + t2] == 0) atomicMin(&s_len, t2);
    }
    __syncthreads();
    const int   len  = s_len;
    const float lenf = (float)len;

    const int j0 = tid * 2;                 // 0,2,..,766
    const int i0 = b * H + j0;

    const uint32_t bits0 = threefry_bits_partitionable((uint32_t)i0);
    const uint32_t bits1 = threefry_bits_partitionable((uint32_t)(i0 + 1));
    const float u0 = __uint_as_float((bits0 >> 9) | 0x3f800000u) - 1.0f;
    const float u1 = __uint_as_float((bits1 >> 9) | 0x3f800000u) - 1.0f;
    int idx0 = (int)floorf(u0 * lenf);
    int idx1 = (int)floorf(u1 * lenf);
    if (idx0 > len - 1) idx0 = len - 1;
    if (idx1 > len - 1) idx1 = len - 1;

    const size_t rowb = (size_t)b * SEQ * H;
    const float e0 = __ldcg(&tokens[rowb + (size_t)idx0 * H + j0]);
    const float e1 = __ldcg(&tokens[rowb + (size_t)idx1 * H + j0 + 1]);
    *reinterpret_cast<float2*>(&g_emb[i0]) = make_float2(e0, e1);
}

// ---------------------------------------------------------------------------
// Kernel 2: TF32 tensor-core GEMM, 4-stage cp.async pipeline.
// Raw f32 bits fed to mma.tf32 (HW reads top 19 bits = tf32 truncation).
// g_S[g] = Xg @ Wg, g in {0,1,2}. BM=64, BN=64, BK=16; 256 threads = 8 warps,
// warp tile 32x16. Grid (12, 12) = 144 blocks (1 wave).
// ---------------------------------------------------------------------------
#define BM     64
#define BN     64
#define BK     16
#define NIT    (H / BK)   // 48
#define NSTAGE 4
#define APAD   20   // As row stride (words): conflict-free frag reads
#define BPAD   72   // Bs row stride (words): conflict-free frag reads
#define A_WORDS (BM * APAD)   // 1280
#define B_WORDS (BK * BPAD)   // 1152

__device__ __forceinline__ void cp16(uint32_t saddr, const void* gaddr) {
    asm volatile("cp.async.ca.shared.global [%0], [%1], 16;\n"
                 :: "r"(saddr), "l"(gaddr));
}
__device__ __forceinline__ void cp_commit() {
    asm volatile("cp.async.commit_group;\n");
}
template <int N>
__device__ __forceinline__ void cp_wait() {
    asm volatile("cp.async.wait_group %0;\n" :: "n"(N));
}

__device__ __forceinline__ void mma_tf32(float* d, const uint32_t* a, const uint32_t* b) {
    asm volatile(
        "mma.sync.aligned.m16n8k8.row.col.f32.tf32.tf32.f32 "
        "{%0,%1,%2,%3}, {%4,%5,%6,%7}, {%8,%9}, {%0,%1,%2,%3};\n"
        : "+f"(d[0]), "+f"(d[1]), "+f"(d[2]), "+f"(d[3])
        : "r"(a[0]), "r"(a[1]), "r"(a[2]), "r"(a[3]), "r"(b[0]), "r"(b[1]));
}

__device__ __forceinline__ void compute_tile(const uint32_t* __restrict__ As,
                                             const uint32_t* __restrict__ Bs,
                                             int wm, int wn, int grp, int tig,
                                             float acc[2][2][4]) {
#pragma unroll
    for (int ks = 0; ks < BK; ks += 8) {
        uint32_t afr[2][4];
#pragma unroll
        for (int mi = 0; mi < 2; mi++) {
            const int rbase = (wm + mi * 16 + grp) * APAD + ks + tig;
            afr[mi][0] = As[rbase];
            afr[mi][1] = As[rbase + 8 * APAD];
            afr[mi][2] = As[rbase + 4];
            afr[mi][3] = As[rbase + 8 * APAD + 4];
        }
        uint32_t bfr[2][2];
#pragma unroll
        for (int ni = 0; ni < 2; ni++) {
            const int cbase = (ks + tig) * BPAD + wn + ni * 8 + grp;
            bfr[ni][0] = Bs[cbase];
            bfr[ni][1] = Bs[cbase + 4 * BPAD];
        }
#pragma unroll
        for (int mi = 0; mi < 2; mi++)
#pragma unroll
            for (int ni = 0; ni < 2; ni++)
                mma_tf32(acc[mi][ni], afr[mi], bfr[ni]);
    }
}

__global__ void __launch_bounds__(256, 1)
gemm_tf32_kernel(const float* __restrict__ cls,
                 const float* __restrict__ W) {
    const int g  = blockIdx.y >> 2;             // group 0..2
    const int m0 = (blockIdx.y & 3) * BM;
    const int n0 = blockIdx.x * BN;

    const float* __restrict__ A  = (g == 2) ? g_emb : cls;
    const float* __restrict__ Wg = W + (g == 0 ? 0 : (size_t)H * H);

    __shared__ uint32_t As[NSTAGE][A_WORDS];
    __shared__ uint32_t Bs[NSTAGE][B_WORDS];

    const int tid  = threadIdx.x;
    const int warp = tid >> 5;
    const int lane = tid & 31;
    const int wm   = (warp & 1) * 32;
    const int wn   = (warp >> 1) * 16;
    const int grp  = lane >> 2;
    const int tig  = lane & 3;

    // staging mapping (one A float4 + one B float4 per thread per stage)
    const int a_r = tid >> 2;            // 0..63
    const int a_c = (tid & 3) * 4;       // 0,4,8,12
    const int b_r = tid >> 4;            // 0..15
    const int b_c = (tid & 15) * 4;      // 0..60

    const float* a_src = &A[(m0 + a_r) * H + a_c];
    const float* b_src = &Wg[(size_t)b_r * H + n0 + b_c];

    const uint32_t s_as = (uint32_t)__cvta_generic_to_shared(&As[0][0]) +
                          (uint32_t)((a_r * APAD + a_c) * 4);
    const uint32_t s_bs = (uint32_t)__cvta_generic_to_shared(&Bs[0][0]) +
                          (uint32_t)((b_r * BPAD + b_c) * 4);

    float acc[2][2][4];
#pragma unroll
    for (int mi = 0; mi < 2; mi++)
#pragma unroll
        for (int ni = 0; ni < 2; ni++)
#pragma unroll
            for (int r = 0; r < 4; r++) acc[mi][ni][r] = 0.0f;

    // prologue: issue stages 0..2
#pragma unroll
    for (int s = 0; s < NSTAGE - 1; s++) {
        cp16(s_as + (uint32_t)(s * A_WORDS * 4), a_src + s * BK);
        cp16(s_bs + (uint32_t)(s * B_WORDS * 4), b_src + (size_t)(s * BK) * H);
        cp_commit();
    }

    for (int it = 0; it < NIT; it++) {
        cp_wait<NSTAGE - 2>();           // tile `it` resident
        __syncthreads();                 // visible to all warps; prev compute done

        const int nx = it + NSTAGE - 1;
        if (nx < NIT) {
            const int buf = nx & (NSTAGE - 1);
            cp16(s_as + (uint32_t)(buf * A_WORDS * 4), a_src + nx * BK);
            cp16(s_bs + (uint32_t)(buf * B_WORDS * 4), b_src + (size_t)(nx * BK) * H);
        }
        cp_commit();                     // commit (possibly empty) to keep counts aligned

        compute_tile(As[it & (NSTAGE - 1)], Bs[it & (NSTAGE - 1)],
                     wm, wn, grp, tig, acc);
    }

    float* __restrict__ Cp = g_S + (size_t)g * BS * H;
#pragma unroll
    for (int mi = 0; mi < 2; mi++) {
#pragma unroll
        for (int ni = 0; ni < 2; ni++) {
            const int col = n0 + wn + ni * 8 + tig * 2;
            const int r0  = m0 + wm + mi * 16 + grp;
            *reinterpret_cast<float2*>(&Cp[(size_t)r0 * H + col]) =
                make_float2(acc[mi][ni][0], acc[mi][ni][1]);
            *reinterpret_cast<float2*>(&Cp[(size_t)(r0 + 8) * H + col]) =
                make_float2(acc[mi][ni][2], acc[mi][ni][3]);
        }
    }
}

// ---------------------------------------------------------------------------
// Kernel 3: energy + alpha. One block per batch, 256 threads, 3 elems each.
// e_k = v . tanh(S0 + S_k + bias); alpha = softmax over {0,1}; g_alpha[b] = a0.
// Single barrier; warp 0 finishes alone (no broadcast phase).
// ---------------------------------------------------------------------------
__global__ void __launch_bounds__(256, 4)
energy_kernel(const float* __restrict__ bias,
              const float* __restrict__ v) {
    const int b   = blockIdx.x;
    const int tid = threadIdx.x;   // 0..255

    float p0 = 0.0f, p1 = 0.0f;
#pragma unroll
    for (int s = 0; s < 3; s++) {
        const int j = tid + s * 256;
        const size_t base = (size_t)b * H + j;
        const float a  = g_S[base];
        const float bb = g_S[(size_t)BS * H + base];
        const float c  = g_S[(size_t)2 * BS * H + base];
        const float bi = bias[j];
        const float vv = v[j];
        p0 += tanhf(a + bb + bi) * vv;
        p1 += tanhf(a + c  + bi) * vv;
    }

#pragma unroll
    for (int off = 16; off > 0; off >>= 1) {
        p0 += __shfl_down_sync(0xffffffffu, p0, off);
        p1 += __shfl_down_sync(0xffffffffu, p1, off);
    }
    __shared__ float r0[8], r1[8];
    const int w = tid >> 5, l = tid & 31;
    if (l == 0) { r0[w] = p0; r1[w] = p1; }
    __syncthreads();
    if (tid == 0) {
        float e0 = 0.0f, e1 = 0.0f;
#pragma unroll
        for (int i = 0; i < 8; i++) { e0 += r0[i]; e1 += r1[i]; }
        const float m  = fmaxf(e0, e1);
        const float w0 = expf(e0 - m);
        const float w1 = expf(e1 - m);
        g_alpha[b] = w0 / (w0 + w1);
    }
}

// ---------------------------------------------------------------------------
// Kernel 4: combine (fully parallel, float4). out = a*cls + (1-a)*emb.
// 49152 threads, 4 elems each.
// ---------------------------------------------------------------------------
__global__ void __launch_bounds__(1024)
combine_kernel(const float* __restrict__ cls,
               float*       __restrict__ out) {
    const int t = blockIdx.x * blockDim.x + threadIdx.x;   // 0..49151
    const int b = t / (H / 4);                              // 192 quads per batch
    const float a0 = g_alpha[b];
    const float a1 = 1.0f - a0;

    const float4 cv = *reinterpret_cast<const float4*>(&cls[(size_t)t * 4]);
    const float4 ev = *reinterpret_cast<const float4*>(&g_emb[(size_t)t * 4]);
    float4 o;
    o.x = a0 * cv.x + a1 * ev.x;
    o.y = a0 * cv.y + a1 * ev.y;
    o.z = a0 * cv.z + a1 * ev.z;
    o.w = a0 * cv.w + a1 * ev.w;
    *reinterpret_cast<float4*>(&out[(size_t)t * 4]) = o;
}

// ---------------------------------------------------------------------------
// kernel_launch — inputs identified BY ELEMENT COUNT
// ---------------------------------------------------------------------------
extern "C" void kernel_launch(void* const* d_in, const int* in_sizes, int n_in,
                              void* d_out, int out_size) {
    const float* tokens = nullptr;
    const float* cls    = nullptr;
    const int*   mask   = nullptr;
    const float* W      = nullptr;
    const float* bias   = nullptr;
    const float* v      = nullptr;

    for (int i = 0; i < n_in; i++) {
        const int sz = in_sizes[i];
        if      (sz == BS * SEQ * H) tokens = (const float*)d_in[i];
        else if (sz == BS * H)       cls    = (const float*)d_in[i];
        else if (sz == BS * SEQ)     mask   = (const int*)  d_in[i];
        else if (sz == 2 * H * H)    W      = (const float*)d_in[i];
        else if (sz == H) {
            if (bias == nullptr)     bias   = (const float*)d_in[i];
            else                     v      = (const float*)d_in[i];
        }
    }
    float* out = (float*)d_out;

    prep_kernel<<<BS, 384>>>(tokens, mask);
    gemm_tf32_kernel<<<dim3(H / BN, 12), 256>>>(cls, W);
    energy_kernel<<<BS, 256>>>(bias, v);
    combine_kernel<<<(BS * H / 4) / 1024, 1024>>>(cls, out);
}

// round 8
// speedup vs baseline: 2.3817x; 1.1099x over previous
#include <cuda_runtime.h>
#include <cstdint>

#define BS   256
#define SEQ  512
#define H    768

// Scratch (no allocations allowed)
__device__ float g_emb[BS * H];          // gathered "embraced" rows
__device__ float g_S[3 * BS * H];        // S0 = cls@Wtop, S1 = cls@Wbot, S2 = emb@Wbot

// ---------------------------------------------------------------------------
// Threefry-2x32, 20 rounds, key = (0, 42), partitionable scheme:
//   bits32(i) = x0 ^ x1 of threefry2x32(key, (0, i))
// ---------------------------------------------------------------------------
__device__ __forceinline__ uint32_t rotl32(uint32_t x, int r) {
    return (x << r) | (x >> (32 - r));
}

__device__ __forceinline__ uint32_t threefry_bits_partitionable(uint32_t i) {
    const uint32_t k0 = 0u, k1 = 42u;
    const uint32_t ks2 = 0x1BD11BDAu ^ k0 ^ k1;
    uint32_t x0 = 0u + k0;
    uint32_t x1 = i  + k1;

#define TF_BLOCK(r0_, r1_, r2_, r3_)                                   \
    x0 += x1; x1 = rotl32(x1, r0_); x1 ^= x0;                          \
    x0 += x1; x1 = rotl32(x1, r1_); x1 ^= x0;                          \
    x0 += x1; x1 = rotl32(x1, r2_); x1 ^= x0;                          \
    x0 += x1; x1 = rotl32(x1, r3_); x1 ^= x0;

    TF_BLOCK(13, 15, 26, 6)   x0 += k1;  x1 += ks2 + 1u;
    TF_BLOCK(17, 29, 16, 24)  x0 += ks2; x1 += k0  + 2u;
    TF_BLOCK(13, 15, 26, 6)   x0 += k0;  x1 += k1  + 3u;
    TF_BLOCK(17, 29, 16, 24)  x0 += k1;  x1 += ks2 + 4u;
    TF_BLOCK(13, 15, 26, 6)   x0 += ks2; x1 += k0  + 5u;
#undef TF_BLOCK
    return x0 ^ x1;
}

// fast tanh via MUFU.EX2: exact limits at +-inf, ~1e-7 rel err elsewhere
__device__ __forceinline__ float fast_tanh(float x) {
    return 1.0f - 2.0f / (__expf(2.0f * x) + 1.0f);
}

// ---------------------------------------------------------------------------
// Kernel 1: fused length-scan + gather. One block per batch, 384 threads,
// 2 elements per thread, L2-only (sector-granular) gather loads.
// ---------------------------------------------------------------------------
__global__ void __launch_bounds__(384, 4)
prep_kernel(const float* __restrict__ tokens,
            const int*   __restrict__ mask) {
    const int b   = blockIdx.x;
    const int tid = threadIdx.x;   // 0..383

    __shared__ int s_len;
    if (tid == 0) s_len = SEQ;
    __syncthreads();
    if (mask[b * SEQ + tid] == 0) atomicMin(&s_len, tid);
    {
        const int t2 = tid + 384;
        if (t2 < SEQ && mask[b * SEQ + t2] == 0) atomicMin(&s_len, t2);
    }
    __syncthreads();
    const int   len  = s_len;
    const float lenf = (float)len;

    const int j0 = tid * 2;                 // 0,2,..,766
    const int i0 = b * H + j0;

    const uint32_t bits0 = threefry_bits_partitionable((uint32_t)i0);
    const uint32_t bits1 = threefry_bits_partitionable((uint32_t)(i0 + 1));
    const float u0 = __uint_as_float((bits0 >> 9) | 0x3f800000u) - 1.0f;
    const float u1 = __uint_as_float((bits1 >> 9) | 0x3f800000u) - 1.0f;
    int idx0 = (int)floorf(u0 * lenf);
    int idx1 = (int)floorf(u1 * lenf);
    if (idx0 > len - 1) idx0 = len - 1;
    if (idx1 > len - 1) idx1 = len - 1;

    const size_t rowb = (size_t)b * SEQ * H;
    const float e0 = __ldcg(&tokens[rowb + (size_t)idx0 * H + j0]);
    const float e1 = __ldcg(&tokens[rowb + (size_t)idx1 * H + j0 + 1]);
    *reinterpret_cast<float2*>(&g_emb[i0]) = make_float2(e0, e1);
}

// ---------------------------------------------------------------------------
// Kernel 2: TF32 tensor-core GEMM, 4-stage cp.async pipeline.
// Raw f32 bits fed to mma.tf32 (HW reads top 19 bits = tf32 truncation).
// g_S[g] = Xg @ Wg, g in {0,1,2}. BM=64, BN=64, BK=16; 256 threads = 8 warps,
// warp tile 32x16. Grid (12, 12) = 144 blocks (1 wave).
// ---------------------------------------------------------------------------
#define BM     64
#define BN     64
#define BK     16
#define NIT    (H / BK)   // 48
#define NSTAGE 4
#define APAD   20
#define BPAD   72
#define A_WORDS (BM * APAD)   // 1280
#define B_WORDS (BK * BPAD)   // 1152

__device__ __forceinline__ void cp16(uint32_t saddr, const void* gaddr) {
    asm volatile("cp.async.ca.shared.global [%0], [%1], 16;\n"
                 :: "r"(saddr), "l"(gaddr));
}
__device__ __forceinline__ void cp_commit() {
    asm volatile("cp.async.commit_group;\n");
}
template <int N>
__device__ __forceinline__ void cp_wait() {
    asm volatile("cp.async.wait_group %0;\n" :: "n"(N));
}

__device__ __forceinline__ void mma_tf32(float* d, const uint32_t* a, const uint32_t* b) {
    asm volatile(
        "mma.sync.aligned.m16n8k8.row.col.f32.tf32.tf32.f32 "
        "{%0,%1,%2,%3}, {%4,%5,%6,%7}, {%8,%9}, {%0,%1,%2,%3};\n"
        : "+f"(d[0]), "+f"(d[1]), "+f"(d[2]), "+f"(d[3])
        : "r"(a[0]), "r"(a[1]), "r"(a[2]), "r"(a[3]), "r"(b[0]), "r"(b[1]));
}

__device__ __forceinline__ void compute_tile(const uint32_t* __restrict__ As,
                                             const uint32_t* __restrict__ Bs,
                                             int wm, int wn, int grp, int tig,
                                             float acc[2][2][4]) {
#pragma unroll
    for (int ks = 0; ks < BK; ks += 8) {
        uint32_t afr[2][4];
#pragma unroll
        for (int mi = 0; mi < 2; mi++) {
            const int rbase = (wm + mi * 16 + grp) * APAD + ks + tig;
            afr[mi][0] = As[rbase];
            afr[mi][1] = As[rbase + 8 * APAD];
            afr[mi][2] = As[rbase + 4];
            afr[mi][3] = As[rbase + 8 * APAD + 4];
        }
        uint32_t bfr[2][2];
#pragma unroll
        for (int ni = 0; ni < 2; ni++) {
            const int cbase = (ks + tig) * BPAD + wn + ni * 8 + grp;
            bfr[ni][0] = Bs[cbase];
            bfr[ni][1] = Bs[cbase + 4 * BPAD];
        }
#pragma unroll
        for (int mi = 0; mi < 2; mi++)
#pragma unroll
            for (int ni = 0; ni < 2; ni++)
                mma_tf32(acc[mi][ni], afr[mi], bfr[ni]);
    }
}

__global__ void __launch_bounds__(256, 1)
gemm_tf32_kernel(const float* __restrict__ cls,
                 const float* __restrict__ W) {
    const int g  = blockIdx.y >> 2;             // group 0..2
    const int m0 = (blockIdx.y & 3) * BM;
    const int n0 = blockIdx.x * BN;

    const float* __restrict__ A  = (g == 2) ? g_emb : cls;
    const float* __restrict__ Wg = W + (g == 0 ? 0 : (size_t)H * H);

    __shared__ uint32_t As[NSTAGE][A_WORDS];
    __shared__ uint32_t Bs[NSTAGE][B_WORDS];

    const int tid  = threadIdx.x;
    const int warp = tid >> 5;
    const int lane = tid & 31;
    const int wm   = (warp & 1) * 32;
    const int wn   = (warp >> 1) * 16;
    const int grp  = lane >> 2;
    const int tig  = lane & 3;

    const int a_r = tid >> 2;
    const int a_c = (tid & 3) * 4;
    const int b_r = tid >> 4;
    const int b_c = (tid & 15) * 4;

    const float* a_src = &A[(m0 + a_r) * H + a_c];
    const float* b_src = &Wg[(size_t)b_r * H + n0 + b_c];

    const uint32_t s_as = (uint32_t)__cvta_generic_to_shared(&As[0][0]) +
                          (uint32_t)((a_r * APAD + a_c) * 4);
    const uint32_t s_bs = (uint32_t)__cvta_generic_to_shared(&Bs[0][0]) +
                          (uint32_t)((b_r * BPAD + b_c) * 4);

    float acc[2][2][4];
#pragma unroll
    for (int mi = 0; mi < 2; mi++)
#pragma unroll
        for (int ni = 0; ni < 2; ni++)
#pragma unroll
            for (int r = 0; r < 4; r++) acc[mi][ni][r] = 0.0f;

#pragma unroll
    for (int s = 0; s < NSTAGE - 1; s++) {
        cp16(s_as + (uint32_t)(s * A_WORDS * 4), a_src + s * BK);
        cp16(s_bs + (uint32_t)(s * B_WORDS * 4), b_src + (size_t)(s * BK) * H);
        cp_commit();
    }

    for (int it = 0; it < NIT; it++) {
        cp_wait<NSTAGE - 2>();
        __syncthreads();

        const int nx = it + NSTAGE - 1;
        if (nx < NIT) {
            const int buf = nx & (NSTAGE - 1);
            cp16(s_as + (uint32_t)(buf * A_WORDS * 4), a_src + nx * BK);
            cp16(s_bs + (uint32_t)(buf * B_WORDS * 4), b_src + (size_t)(nx * BK) * H);
        }
        cp_commit();

        compute_tile(As[it & (NSTAGE - 1)], Bs[it & (NSTAGE - 1)],
                     wm, wn, grp, tig, acc);
    }

    float* __restrict__ Cp = g_S + (size_t)g * BS * H;
#pragma unroll
    for (int mi = 0; mi < 2; mi++) {
#pragma unroll
        for (int ni = 0; ni < 2; ni++) {
            const int col = n0 + wn + ni * 8 + tig * 2;
            const int r0  = m0 + wm + mi * 16 + grp;
            *reinterpret_cast<float2*>(&Cp[(size_t)r0 * H + col]) =
                make_float2(acc[mi][ni][0], acc[mi][ni][1]);
            *reinterpret_cast<float2*>(&Cp[(size_t)(r0 + 8) * H + col]) =
                make_float2(acc[mi][ni][2], acc[mi][ni][3]);
        }
    }
}

// ---------------------------------------------------------------------------
// Kernel 3: fused epilogue. One block per batch, 768 threads.
// ALL global loads issued up front (independent batch), then:
// e_k = v . tanh(S0 + S_k + bias); alpha = softmax; out = a0*cls + a1*emb.
// ---------------------------------------------------------------------------
__global__ void __launch_bounds__(768, 2)
epilogue_kernel(const float* __restrict__ cls,
                const float* __restrict__ bias,
                const float* __restrict__ v,
                float*       __restrict__ out) {
    const int b   = blockIdx.x;
    const int tid = threadIdx.x;   // 0..767

    const size_t base = (size_t)b * H + tid;

    // --- issue every load up front; all independent ---
    const float cv = cls[base];
    const float ev = g_emb[base];
    const float a  = g_S[base];
    const float bb = g_S[(size_t)BS * H + base];
    const float c  = g_S[(size_t)2 * BS * H + base];
    const float bi = bias[tid];
    const float vv = v[tid];

    float p0 = fast_tanh(a + bb + bi) * vv;
    float p1 = fast_tanh(a + c  + bi) * vv;

#pragma unroll
    for (int off = 16; off > 0; off >>= 1) {
        p0 += __shfl_down_sync(0xffffffffu, p0, off);
        p1 += __shfl_down_sync(0xffffffffu, p1, off);
    }
    __shared__ float r0[24], r1[24];
    __shared__ float s_alpha;
    const int w = tid >> 5, l = tid & 31;
    if (l == 0) { r0[w] = p0; r1[w] = p1; }
    __syncthreads();
    if (tid == 0) {
        float e0 = 0.0f, e1 = 0.0f;
#pragma unroll
        for (int i = 0; i < 24; i++) { e0 += r0[i]; e1 += r1[i]; }
        const float m  = fmaxf(e0, e1);
        const float w0 = __expf(e0 - m);
        const float w1 = __expf(e1 - m);
        s_alpha = w0 / (w0 + w1);
    }
    __syncthreads();
    const float a0 = s_alpha;
    out[base] = a0 * cv + (1.0f - a0) * ev;
}

// ---------------------------------------------------------------------------
// kernel_launch — inputs identified BY ELEMENT COUNT
// ---------------------------------------------------------------------------
extern "C" void kernel_launch(void* const* d_in, const int* in_sizes, int n_in,
                              void* d_out, int out_size) {
    const float* tokens = nullptr;
    const float* cls    = nullptr;
    const int*   mask   = nullptr;
    const float* W      = nullptr;
    const float* bias   = nullptr;
    const float* v      = nullptr;

    for (int i = 0; i < n_in; i++) {
        const int sz = in_sizes[i];
        if      (sz == BS * SEQ * H) tokens = (const float*)d_in[i];
        else if (sz == BS * H)       cls    = (const float*)d_in[i];
        else if (sz == BS * SEQ)     mask   = (const int*)  d_in[i];
        else if (sz == 2 * H * H)    W      = (const float*)d_in[i];
        else if (sz == H) {
            if (bias == nullptr)     bias   = (const float*)d_in[i];
            else                     v      = (const float*)d_in[i];
        }
    }
    float* out = (float*)d_out;

    prep_kernel<<<BS, 384>>>(tokens, mask);
    gemm_tf32_kernel<<<dim3(H / BN, 12), 256>>>(cls, W);
    epilogue_kernel<<<BS, 768>>>(cls, bias, v, out);
}